// round 2
// baseline (speedup 1.0000x reference)
#include <cuda_runtime.h>
#include <math.h>

#define B_ 8
#define Q_ 150
#define C_ 134
#define T_ 32
#define H_ 160
#define W_ 160
#define P_ 12544
#define HW_ (H_ * W_)

// Scratch (static device allocations are allowed; dynamic alloc is not)
__device__ __align__(128) float g_tmT[(size_t)B_ * T_ * P_];  // [b][t][p]
__device__ __align__(128) float g_tm [(size_t)B_ * T_ * P_];  // [b][p][t]
__device__ float g_Stm[B_ * T_];

// Bilinear sample (align_corners=False, zero padding) from an HxW mask in smem.
__device__ __forceinline__ float sample_smem(const float* sm, float cx, float cy) {
    float x = cx * (float)W_ - 0.5f;
    float y = cy * (float)H_ - 0.5f;
    float fx = floorf(x), fy = floorf(y);
    float tx = x - fx, ty = y - fy;
    int x0 = (int)fx, y0 = (int)fy;       // x0 in [-1,159], x0+1 in [0,160]
    float wx0 = (1.f - tx) * (x0 >= 0 ? 1.f : 0.f);
    float wx1 = tx         * (x0 < W_ - 1 ? 1.f : 0.f);
    float wy0 = (1.f - ty) * (y0 >= 0 ? 1.f : 0.f);
    float wy1 = ty         * (y0 < H_ - 1 ? 1.f : 0.f);
    int xc0 = max(x0, 0);
    int xc1 = min(x0 + 1, W_ - 1);
    int yc0 = max(y0, 0);
    int yc1 = min(y0 + 1, H_ - 1);
    float r0 = wx0 * sm[yc0 * W_ + xc0] + wx1 * sm[yc0 * W_ + xc1];
    float r1 = wx0 * sm[yc1 * W_ + xc0] + wx1 * sm[yc1 * W_ + xc1];
    return wy0 * r0 + wy1 * r1;
}

// Kernel 1: sample target masks at all points. Grid (T_, B_), 256 threads.
// smem: HW_ floats (mask) + 8 floats (warp sums)
__global__ __launch_bounds__(256) void k_sample_tgt(
    const float* __restrict__ tgt, const float* __restrict__ coords) {
    extern __shared__ float s_[];
    float* sm  = s_;
    float* swr = s_ + HW_;
    int t = blockIdx.x, b = blockIdx.y;
    int tid = threadIdx.x;

    const float4* m4 = (const float4*)(tgt + ((size_t)(b * T_ + t)) * HW_);
    float4* d4 = (float4*)sm;
    for (int i = tid; i < HW_ / 4; i += 256) d4[i] = m4[i];
    __syncthreads();

    const float2* cp = (const float2*)coords + (size_t)b * P_;
    float* out = g_tmT + ((size_t)(b * T_ + t)) * P_;
    float sum = 0.f;
    for (int p = tid; p < P_; p += 256) {
        float2 c = cp[p];
        float v = sample_smem(sm, c.x, c.y);
        out[p] = v;
        sum += v;
    }
    #pragma unroll
    for (int off = 16; off; off >>= 1) sum += __shfl_xor_sync(~0u, sum, off);
    if ((tid & 31) == 0) swr[tid >> 5] = sum;
    __syncthreads();
    if (tid == 0) {
        float s = 0.f;
        #pragma unroll
        for (int w = 0; w < 8; w++) s += swr[w];
        g_Stm[b * T_ + t] = s;
    }
}

// Kernel 1.5: transpose [b][t][p] -> [b][p][t]. Grid (P_/64, B_), 256 threads.
__global__ __launch_bounds__(256) void k_transpose() {
    __shared__ float tile[32 * 65];
    int b = blockIdx.y;
    int p0 = blockIdx.x * 64;
    for (int e = threadIdx.x; e < 2048; e += 256) {
        int t = e >> 6, pl = e & 63;
        tile[t * 65 + pl] = g_tmT[((size_t)(b * T_ + t)) * P_ + p0 + pl];
    }
    __syncthreads();
    for (int o = threadIdx.x; o < 2048; o += 256) {
        int pl = o >> 5, t = o & 31;
        g_tm[((size_t)(b * P_ + p0 + pl)) * T_ + t] = tile[t * 65 + pl];
    }
}

// Kernel 2: main cost kernel. Grid (Q_, B_), 256 threads.
// smem: mask HW_ + cls 136 + redA 256 + redD 256 + redS 16
__global__ __launch_bounds__(256) void k_main(
    const float* __restrict__ pmask, const float* __restrict__ clslog,
    const int* __restrict__ labels, const float* __restrict__ coords,
    float* __restrict__ out) {
    extern __shared__ float s_[];
    float* sm   = s_;
    float* scls = s_ + HW_;
    float* redA = scls + 136;
    float* redD = redA + 256;
    float* redS = redD + 256;
    int q = blockIdx.x, b = blockIdx.y;
    int tid = threadIdx.x;

    const float4* m4 = (const float4*)(pmask + ((size_t)(b * Q_ + q)) * HW_);
    float4* d4 = (float4*)sm;
    for (int i = tid; i < HW_ / 4; i += 256) d4[i] = m4[i];
    if (tid < C_) scls[tid] = clslog[((size_t)(b * Q_ + q)) * C_ + tid];
    __syncthreads();

    float accA[T_], accD[T_];
    #pragma unroll
    for (int t = 0; t < T_; t++) { accA[t] = 0.f; accD[t] = 0.f; }
    float sNeg = 0.f, sSig = 0.f;

    const float2* cp = (const float2*)coords + (size_t)b * P_;
    for (int p = tid; p < P_; p += 256) {
        float2 c = cp[p];
        float pm = sample_smem(sm, c.x, c.y);
        // stable sigmoid + softplus via e^{-|pm|}
        float ea  = __expf(-fabsf(pm));
        float r   = __frcp_rn(1.f + ea);
        float sig = (pm >= 0.f) ? r : ea * r;
        float sp  = fmaxf(pm, 0.f) + __logf(1.f + ea);  // softplus(pm)
        sSig += sig;
        sNeg += sp;
        const float4* tr = (const float4*)(g_tm + ((size_t)(b * P_ + p)) * T_);
        #pragma unroll
        for (int j = 0; j < 8; j++) {
            float4 v = tr[j];
            accA[4 * j + 0] = fmaf(pm,  v.x, accA[4 * j + 0]);
            accD[4 * j + 0] = fmaf(sig, v.x, accD[4 * j + 0]);
            accA[4 * j + 1] = fmaf(pm,  v.y, accA[4 * j + 1]);
            accD[4 * j + 1] = fmaf(sig, v.y, accD[4 * j + 1]);
            accA[4 * j + 2] = fmaf(pm,  v.z, accA[4 * j + 2]);
            accD[4 * j + 2] = fmaf(sig, v.z, accD[4 * j + 2]);
            accA[4 * j + 3] = fmaf(pm,  v.w, accA[4 * j + 3]);
            accD[4 * j + 3] = fmaf(sig, v.w, accD[4 * j + 3]);
        }
    }

    // Deterministic tree reduction: warp shuffle, then cross-warp via smem.
    int wid = tid >> 5, lane = tid & 31;
    #pragma unroll
    for (int t = 0; t < T_; t++) {
        float a = accA[t], d = accD[t];
        #pragma unroll
        for (int off = 16; off; off >>= 1) {
            a += __shfl_xor_sync(~0u, a, off);
            d += __shfl_xor_sync(~0u, d, off);
        }
        if (lane == 0) { redA[wid * 32 + t] = a; redD[wid * 32 + t] = d; }
    }
    {
        float a = sNeg, d = sSig;
        #pragma unroll
        for (int off = 16; off; off >>= 1) {
            a += __shfl_xor_sync(~0u, a, off);
            d += __shfl_xor_sync(~0u, d, off);
        }
        if (lane == 0) { redS[wid] = a; redS[8 + wid] = d; }
    }
    __syncthreads();

    if (wid == 0) {
        int t = lane;  // lane == t index, T_ == 32
        float A = 0.f, D = 0.f, Sneg = 0.f, Ssig = 0.f;
        #pragma unroll
        for (int w = 0; w < 8; w++) {
            A    += redA[w * 32 + t];
            D    += redD[w * 32 + t];
            Sneg += redS[w];
            Ssig += redS[8 + w];
        }
        // class softmax over C_=134 within warp 0
        float lmax = -1e30f;
        for (int c = lane; c < C_; c += 32) lmax = fmaxf(lmax, scls[c]);
        #pragma unroll
        for (int off = 16; off; off >>= 1)
            lmax = fmaxf(lmax, __shfl_xor_sync(~0u, lmax, off));
        float lsum = 0.f;
        for (int c = lane; c < C_; c += 32) lsum += __expf(scls[c] - lmax);
        #pragma unroll
        for (int off = 16; off; off >>= 1)
            lsum += __shfl_xor_sync(~0u, lsum, off);

        int lbl = labels[b * T_ + t];
        lbl = min(max(lbl, 0), C_ - 1);  // defensive clamp (labels in [0,133))
        float cost_class = -__expf(scls[lbl] - lmax) / lsum;
        float Stm = g_Stm[b * T_ + t];
        float cost_mask = 5.f * (Sneg - A) * (1.f / (float)P_);
        float cost_dice = 5.f * (1.f - (2.f * D + 1.f) / (Ssig + Stm + 1.f));
        out[((size_t)(b * Q_ + q)) * T_ + t] = cost_mask + cost_class + cost_dice;
    }
}

extern "C" void kernel_launch(void* const* d_in, const int* in_sizes, int n_in,
                              void* d_out, int out_size) {
    const float* pmask  = (const float*)d_in[0];      // [8,150,160,160]
    const float* clslog = (const float*)d_in[1];      // [8,150,134]
    const float* tmask  = (const float*)d_in[2];      // [8,32,160,160]
    const int*   labels = (const int*)d_in[3];        // [8,32] int32
    const float* coords = (const float*)d_in[4];      // [8,12544,2]
    float* out = (float*)d_out;                       // [8,150,32]

    const int smem1 = (HW_ + 8) * 4;                      // 102432
    const int smem2 = (HW_ + 136 + 256 + 256 + 16) * 4;   // 105056
    cudaFuncSetAttribute(k_sample_tgt, cudaFuncAttributeMaxDynamicSharedMemorySize, smem1);
    cudaFuncSetAttribute(k_main,       cudaFuncAttributeMaxDynamicSharedMemorySize, smem2);

    k_sample_tgt<<<dim3(T_, B_), 256, smem1>>>(tmask, coords);
    k_transpose<<<dim3(P_ / 64, B_), 256>>>();
    k_main<<<dim3(Q_, B_), 256, smem2>>>(pmask, clslog, labels, coords, out);
}

// round 3
// speedup vs baseline: 2.2935x; 2.2935x over previous
#include <cuda_runtime.h>
#include <cuda_fp16.h>
#include <math.h>

#define B_ 8
#define Q_ 150
#define C_ 134
#define T_ 32
#define H_ 160
#define W_ 160
#define P_ 12544
#define HW_ (H_ * W_)

// Scratch (static device arrays; dynamic alloc forbidden)
__device__ __align__(128) __half g_tmT[(size_t)B_ * T_ * P_];  // [b][t][p] fp16
__device__ __align__(128) __half g_tm [(size_t)B_ * P_ * T_];  // [b][p][t] fp16, 64B/point
__device__ float g_Stm[B_ * T_];

// Bilinear sample (align_corners=False, zero padding) from an HxW mask in smem.
__device__ __forceinline__ float sample_smem(const float* sm, float cx, float cy) {
    float x = cx * (float)W_ - 0.5f;
    float y = cy * (float)H_ - 0.5f;
    float fx = floorf(x), fy = floorf(y);
    float tx = x - fx, ty = y - fy;
    int x0 = (int)fx, y0 = (int)fy;  // x0 in [-1,159], x0+1 in [0,160]
    float wx0 = (1.f - tx) * (x0 >= 0 ? 1.f : 0.f);
    float wx1 = tx         * (x0 < W_ - 1 ? 1.f : 0.f);
    float wy0 = (1.f - ty) * (y0 >= 0 ? 1.f : 0.f);
    float wy1 = ty         * (y0 < H_ - 1 ? 1.f : 0.f);
    int xc0 = max(x0, 0);
    int xc1 = min(x0 + 1, W_ - 1);
    int yc0 = max(y0, 0);
    int yc1 = min(y0 + 1, H_ - 1);
    float r0 = wx0 * sm[yc0 * W_ + xc0] + wx1 * sm[yc0 * W_ + xc1];
    float r1 = wx0 * sm[yc1 * W_ + xc0] + wx1 * sm[yc1 * W_ + xc1];
    return wy0 * r0 + wy1 * r1;
}

// Kernel 1: sample target masks at all points. Grid (T_, B_), 512 threads.
// smem: HW_ floats (mask) + 16 floats (warp sums)
__global__ __launch_bounds__(512) void k_sample_tgt(
    const float* __restrict__ tgt, const float* __restrict__ coords) {
    extern __shared__ float s_[];
    float* sm  = s_;
    float* swr = s_ + HW_;
    int t = blockIdx.x, b = blockIdx.y;
    int tid = threadIdx.x;

    const float4* m4 = (const float4*)(tgt + ((size_t)(b * T_ + t)) * HW_);
    float4* d4 = (float4*)sm;
    for (int i = tid; i < HW_ / 4; i += 512) d4[i] = m4[i];
    __syncthreads();

    const float2* cp = (const float2*)coords + (size_t)b * P_;
    __half* out = g_tmT + ((size_t)(b * T_ + t)) * P_;
    float sum = 0.f;
    for (int p = tid; p < P_; p += 512) {
        float2 c = cp[p];
        float v = sample_smem(sm, c.x, c.y);
        out[p] = __float2half_rn(v);
        sum += v;
    }
    #pragma unroll
    for (int off = 16; off; off >>= 1) sum += __shfl_xor_sync(~0u, sum, off);
    if ((tid & 31) == 0) swr[tid >> 5] = sum;
    __syncthreads();
    if (tid == 0) {
        float s = 0.f;
        #pragma unroll
        for (int w = 0; w < 16; w++) s += swr[w];
        g_Stm[b * T_ + t] = s;
    }
}

// Kernel 1.5: transpose fp16 [b][t][p] -> [b][p][t]. Grid (P_/64, B_), 256 threads.
__global__ __launch_bounds__(256) void k_transpose() {
    __shared__ __half tile[32][66];
    int b = blockIdx.y;
    int p0 = blockIdx.x * 64;
    for (int e = threadIdx.x; e < 2048; e += 256) {
        int t = e >> 6, pl = e & 63;
        tile[t][pl] = g_tmT[((size_t)(b * T_ + t)) * P_ + p0 + pl];
    }
    __syncthreads();
    // 1024 half2 outputs: pl in [0,64), j in [0,16) -> (t=2j, t=2j+1)
    __half2* o2 = (__half2*)(g_tm + ((size_t)b * P_ + p0) * T_);
    for (int o = threadIdx.x; o < 1024; o += 256) {
        int pl = o >> 4, j = o & 15;
        __half2 v = __halves2half2(tile[2 * j][pl], tile[2 * j + 1][pl]);
        o2[pl * 16 + j] = v;
    }
}

// Kernel 2: main cost kernel. Grid (Q_, B_), 256 threads, 2 CTAs/SM.
// smem: mask HW_ + cls 136 + redA 256 + redD 256 + redS 16
__global__ __launch_bounds__(256, 2) void k_main(
    const float* __restrict__ pmask, const float* __restrict__ clslog,
    const int* __restrict__ labels, const float* __restrict__ coords,
    float* __restrict__ out) {
    extern __shared__ float s_[];
    float* sm   = s_;
    float* scls = s_ + HW_;
    float* redA = scls + 136;
    float* redD = redA + 256;
    float* redS = redD + 256;
    int q = blockIdx.x, b = blockIdx.y;
    int tid = threadIdx.x;

    const float4* m4 = (const float4*)(pmask + ((size_t)(b * Q_ + q)) * HW_);
    float4* d4 = (float4*)sm;
    for (int i = tid; i < HW_ / 4; i += 256) d4[i] = m4[i];
    if (tid < C_) scls[tid] = clslog[((size_t)(b * Q_ + q)) * C_ + tid];
    __syncthreads();

    // fp16 accumulators: hA[j] holds targets (2j, 2j+1)
    __half2 hA[16], hD[16];
    #pragma unroll
    for (int j = 0; j < 16; j++) {
        hA[j] = __float2half2_rn(0.f);
        hD[j] = __float2half2_rn(0.f);
    }
    float sNeg = 0.f, sSig = 0.f;

    const float2* cp = (const float2*)coords + (size_t)b * P_;
    const uint4* tmb = (const uint4*)(g_tm + (size_t)b * P_ * T_);  // 4 uint4 / point

    #pragma unroll 7
    for (int it = 0; it < 49; it++) {
        int p = tid + it * 256;
        float2 c = cp[p];
        union { uint4 u[4]; __half2 h[16]; } tm;
        tm.u[0] = tmb[(size_t)p * 4 + 0];
        tm.u[1] = tmb[(size_t)p * 4 + 1];
        tm.u[2] = tmb[(size_t)p * 4 + 2];
        tm.u[3] = tmb[(size_t)p * 4 + 3];

        float pm = sample_smem(sm, c.x, c.y);
        // stable sigmoid + softplus via e^{-|pm|}
        float ea  = __expf(-fabsf(pm));
        float r   = __frcp_rn(1.f + ea);
        float sig = (pm >= 0.f) ? r : ea * r;
        float sp  = fmaxf(pm, 0.f) + __logf(1.f + ea);  // softplus(pm)
        sSig += sig;
        sNeg += sp;

        __half2 pmh = __float2half2_rn(pm);
        __half2 sgh = __float2half2_rn(sig);
        #pragma unroll
        for (int j = 0; j < 16; j++) {
            hA[j] = __hfma2(pmh, tm.h[j], hA[j]);
            hD[j] = __hfma2(sgh, tm.h[j], hD[j]);
        }
    }

    // Deterministic tree reduction: warp shuffle, then cross-warp via smem.
    int wid = tid >> 5, lane = tid & 31;
    #pragma unroll
    for (int j = 0; j < 16; j++) {
        float2 a2 = __half22float2(hA[j]);
        float2 d2 = __half22float2(hD[j]);
        float a0 = a2.x, a1 = a2.y, d0 = d2.x, d1 = d2.y;
        #pragma unroll
        for (int off = 16; off; off >>= 1) {
            a0 += __shfl_xor_sync(~0u, a0, off);
            a1 += __shfl_xor_sync(~0u, a1, off);
            d0 += __shfl_xor_sync(~0u, d0, off);
            d1 += __shfl_xor_sync(~0u, d1, off);
        }
        if (lane == 0) {
            redA[wid * 32 + 2 * j]     = a0;
            redA[wid * 32 + 2 * j + 1] = a1;
            redD[wid * 32 + 2 * j]     = d0;
            redD[wid * 32 + 2 * j + 1] = d1;
        }
    }
    {
        float a = sNeg, d = sSig;
        #pragma unroll
        for (int off = 16; off; off >>= 1) {
            a += __shfl_xor_sync(~0u, a, off);
            d += __shfl_xor_sync(~0u, d, off);
        }
        if (lane == 0) { redS[wid] = a; redS[8 + wid] = d; }
    }
    __syncthreads();

    if (wid == 0) {
        int t = lane;  // lane == target index (T_ == 32)
        float A = 0.f, D = 0.f, Sneg = 0.f, Ssig = 0.f;
        #pragma unroll
        for (int w = 0; w < 8; w++) {
            A    += redA[w * 32 + t];
            D    += redD[w * 32 + t];
            Sneg += redS[w];
            Ssig += redS[8 + w];
        }
        // class softmax over C_=134 within warp 0
        float lmax = -1e30f;
        for (int c = lane; c < C_; c += 32) lmax = fmaxf(lmax, scls[c]);
        #pragma unroll
        for (int off = 16; off; off >>= 1)
            lmax = fmaxf(lmax, __shfl_xor_sync(~0u, lmax, off));
        float lsum = 0.f;
        for (int c = lane; c < C_; c += 32) lsum += __expf(scls[c] - lmax);
        #pragma unroll
        for (int off = 16; off; off >>= 1)
            lsum += __shfl_xor_sync(~0u, lsum, off);

        int lbl = labels[b * T_ + t];
        lbl = min(max(lbl, 0), C_ - 1);  // defensive clamp
        float cost_class = -__expf(scls[lbl] - lmax) / lsum;
        float Stm = g_Stm[b * T_ + t];
        float cost_mask = 5.f * (Sneg - A) * (1.f / (float)P_);
        float cost_dice = 5.f * (1.f - (2.f * D + 1.f) / (Ssig + Stm + 1.f));
        out[((size_t)(b * Q_ + q)) * T_ + t] = cost_mask + cost_class + cost_dice;
    }
}

extern "C" void kernel_launch(void* const* d_in, const int* in_sizes, int n_in,
                              void* d_out, int out_size) {
    const float* pmask  = (const float*)d_in[0];      // [8,150,160,160]
    const float* clslog = (const float*)d_in[1];      // [8,150,134]
    const float* tmask  = (const float*)d_in[2];      // [8,32,160,160]
    const int*   labels = (const int*)d_in[3];        // [8,32] int32
    const float* coords = (const float*)d_in[4];      // [8,12544,2]
    float* out = (float*)d_out;                       // [8,150,32]

    const int smem1 = (HW_ + 16) * 4;                     // ~102.5 KB
    const int smem2 = (HW_ + 136 + 256 + 256 + 16) * 4;   // ~105 KB
    cudaFuncSetAttribute(k_sample_tgt, cudaFuncAttributeMaxDynamicSharedMemorySize, smem1);
    cudaFuncSetAttribute(k_main,       cudaFuncAttributeMaxDynamicSharedMemorySize, smem2);

    k_sample_tgt<<<dim3(T_, B_), 512, smem1>>>(tmask, coords);
    k_transpose<<<dim3(P_ / 64, B_), 256>>>();
    k_main<<<dim3(Q_, B_), 256, smem2>>>(pmask, clslog, labels, coords, out);
}

// round 5
// speedup vs baseline: 2.6626x; 1.1609x over previous
#include <cuda_runtime.h>
#include <cuda_fp16.h>
#include <math.h>

#define B_ 8
#define Q_ 150
#define C_ 134
#define T_ 32
#define H_ 160
#define W_ 160
#define P_ 12544
#define HW_ (H_ * W_)
#define MPAD 192           // Q padded to 3 x 64
#define KSLAB 14
#define KCH 896            // P_/KSLAB
#define NSTAGE 14          // KCH/64

// Static scratch (zero-initialized at module load; rows q>=150 of g_pm/g_sig
// are never written and stay 0 -> padded GEMM rows contribute nothing).
__device__ __align__(128) __half g_tmT[(size_t)B_ * T_ * P_];      // [b][t][p]
__device__ __align__(128) __half g_pm [(size_t)B_ * MPAD * P_];    // [b][q][p]
__device__ __align__(128) __half g_sig[(size_t)B_ * MPAD * P_];    // [b][q][p]
__device__ float g_S[B_ * Q_ * 2];                                 // Sneg, Ssig
__device__ float g_Stm[B_ * T_];
__device__ __align__(128) float g_part[(size_t)B_ * KSLAB * 2 * MPAD * T_];

// Bilinear sample (align_corners=False, zero padding) from an HxW mask in smem.
__device__ __forceinline__ float sample_smem(const float* sm, float cx, float cy) {
    float x = cx * (float)W_ - 0.5f;
    float y = cy * (float)H_ - 0.5f;
    float fx = floorf(x), fy = floorf(y);
    float tx = x - fx, ty = y - fy;
    int x0 = (int)fx, y0 = (int)fy;
    float wx0 = (1.f - tx) * (x0 >= 0 ? 1.f : 0.f);
    float wx1 = tx         * (x0 < W_ - 1 ? 1.f : 0.f);
    float wy0 = (1.f - ty) * (y0 >= 0 ? 1.f : 0.f);
    float wy1 = ty         * (y0 < H_ - 1 ? 1.f : 0.f);
    int xc0 = max(x0, 0);
    int xc1 = min(x0 + 1, W_ - 1);
    int yc0 = max(y0, 0);
    int yc1 = min(y0 + 1, H_ - 1);
    float r0 = wx0 * sm[yc0 * W_ + xc0] + wx1 * sm[yc0 * W_ + xc1];
    float r1 = wx0 * sm[yc1 * W_ + xc0] + wx1 * sm[yc1 * W_ + xc1];
    return wy0 * r0 + wy1 * r1;
}

// Unified sampler. Grid (T_ + Q_, B_), 256 threads.
// blockIdx.x < T_  : target mask t   -> g_tmT[b][t][p] + g_Stm
// blockIdx.x >= T_ : pred mask  q    -> g_pm/g_sig[b][q][p] + g_S
__global__ __launch_bounds__(256) void k_sample(
    const float* __restrict__ pmask, const float* __restrict__ tgt,
    const float* __restrict__ coords) {
    extern __shared__ float s_[];
    float* sm  = s_;
    float* swr = s_ + HW_;
    int bx = blockIdx.x, b = blockIdx.y;
    int tid = threadIdx.x;
    bool is_tgt = bx < T_;

    const float* src = is_tgt ? tgt + ((size_t)(b * T_ + bx)) * HW_
                              : pmask + ((size_t)(b * Q_ + (bx - T_))) * HW_;
    const float4* m4 = (const float4*)src;
    float4* d4 = (float4*)sm;
    for (int i = tid; i < HW_ / 4; i += 256) d4[i] = m4[i];
    __syncthreads();

    const float2* cp = (const float2*)coords + (size_t)b * P_;

    if (is_tgt) {
        int t = bx;
        __half* out = g_tmT + ((size_t)(b * T_ + t)) * P_;
        float sum = 0.f;
        #pragma unroll 7
        for (int it = 0; it < 49; it++) {
            int p = tid + it * 256;
            float2 c = cp[p];
            float v = sample_smem(sm, c.x, c.y);
            out[p] = __float2half_rn(v);
            sum += v;
        }
        #pragma unroll
        for (int off = 16; off; off >>= 1) sum += __shfl_xor_sync(~0u, sum, off);
        if ((tid & 31) == 0) swr[tid >> 5] = sum;
        __syncthreads();
        if (tid == 0) {
            float s = 0.f;
            #pragma unroll
            for (int w = 0; w < 8; w++) s += swr[w];
            g_Stm[b * T_ + t] = s;
        }
    } else {
        int q = bx - T_;
        __half* opm = g_pm  + ((size_t)(b * MPAD + q)) * P_;
        __half* osg = g_sig + ((size_t)(b * MPAD + q)) * P_;
        float sNeg = 0.f, sSig = 0.f;
        #pragma unroll 7
        for (int it = 0; it < 49; it++) {
            int p = tid + it * 256;
            float2 c = cp[p];
            float pm = sample_smem(sm, c.x, c.y);
            float ea  = __expf(-fabsf(pm));
            float r   = __frcp_rn(1.f + ea);
            float sig = (pm >= 0.f) ? r : ea * r;
            float sp  = fmaxf(pm, 0.f) + __logf(1.f + ea);  // softplus(pm)
            sSig += sig;
            sNeg += sp;
            opm[p] = __float2half_rn(pm);
            osg[p] = __float2half_rn(sig);
        }
        #pragma unroll
        for (int off = 16; off; off >>= 1) {
            sNeg += __shfl_xor_sync(~0u, sNeg, off);
            sSig += __shfl_xor_sync(~0u, sSig, off);
        }
        if ((tid & 31) == 0) { swr[tid >> 5] = sNeg; swr[8 + (tid >> 5)] = sSig; }
        __syncthreads();
        if (tid == 0) {
            float a = 0.f, d = 0.f;
            #pragma unroll
            for (int w = 0; w < 8; w++) { a += swr[w]; d += swr[8 + w]; }
            g_S[(b * Q_ + q) * 2 + 0] = a;
            g_S[(b * Q_ + q) * 2 + 1] = d;
        }
    }
}

__device__ __forceinline__ void mma16816(float* c, unsigned a0, unsigned a1,
                                         unsigned a2, unsigned a3,
                                         unsigned b0, unsigned b1) {
    asm volatile(
        "mma.sync.aligned.m16n8k16.row.col.f32.f16.f16.f32 "
        "{%0,%1,%2,%3},{%4,%5,%6,%7},{%8,%9},{%0,%1,%2,%3};\n"
        : "+f"(c[0]), "+f"(c[1]), "+f"(c[2]), "+f"(c[3])
        : "r"(a0), "r"(a1), "r"(a2), "r"(a3), "r"(b0), "r"(b1));
}

// Batched split-K GEMM on tensor cores.
// C_A[q,t] = sum_p pm[q,p]*tmT[t,p]; C_D likewise with sig.
// Grid (3 mblk, KSLAB, B_), 256 threads = 8 warps (4 m-warps x 2 n-warps).
__global__ __launch_bounds__(256) void k_gemm() {
    __shared__ uint4 sApm[2][512];   // 64 rows x 8 granules(16B), XOR-swizzled
    __shared__ uint4 sAsg[2][512];
    __shared__ uint4 sB[2][256];     // 32 rows x 8 granules
    int mblk = blockIdx.x, ks = blockIdx.y, b = blockIdx.z;
    int tid = threadIdx.x;
    int q0 = mblk * 64;
    size_t baseA = ((size_t)b * MPAD + q0) * P_ + (size_t)ks * KCH;
    size_t baseB = ((size_t)b * T_) * P_ + (size_t)ks * KCH;

    auto stage = [&](int s, int buf) {
        int kg = s * 64;
        #pragma unroll
        for (int i = 0; i < 5; i++) {
            int gid = tid + i * 256;
            const __half* src;
            uint4* dst;
            int r, c;
            if (gid < 512) {
                r = gid >> 3; c = gid & 7;
                src = g_pm + baseA + (size_t)r * P_ + kg + c * 8;
                dst = &sApm[buf][0];
            } else if (gid < 1024) {
                int g2 = gid - 512; r = g2 >> 3; c = g2 & 7;
                src = g_sig + baseA + (size_t)r * P_ + kg + c * 8;
                dst = &sAsg[buf][0];
            } else {
                int g2 = gid - 1024; r = g2 >> 3; c = g2 & 7;
                src = g_tmT + baseB + (size_t)r * P_ + kg + c * 8;
                dst = &sB[buf][0];
            }
            unsigned d32 = (unsigned)__cvta_generic_to_shared(dst + r * 8 + (c ^ (r & 7)));
            asm volatile("cp.async.cg.shared.global [%0], [%1], 16;\n"
                         :: "r"(d32), "l"(src));
        }
        asm volatile("cp.async.commit_group;\n");
    };

    int warp = tid >> 5, lane = tid & 31;
    int mw = warp >> 1, nw = warp & 1;
    int lm = lane >> 3, l7 = lane & 7;
    int arow = mw * 16 + ((lm & 1) << 3) + l7;   // A ldmatrix row per lane
    int agadd = lm >> 1;                          // k8-half select
    int brow = nw * 16 + ((lm >> 1) << 3) + l7;  // B ldmatrix row per lane
    int bgadd = lm & 1;

    float cA[2][4] = {}, cD[2][4] = {};

    stage(0, 0);
    for (int s = 0; s < NSTAGE; s++) {
        int buf = s & 1;
        if (s + 1 < NSTAGE) {
            stage(s + 1, buf ^ 1);
            asm volatile("cp.async.wait_group 1;\n");
        } else {
            asm volatile("cp.async.wait_group 0;\n");
        }
        __syncthreads();
        unsigned bApm = (unsigned)__cvta_generic_to_shared(&sApm[buf][0]);
        unsigned bAsg = (unsigned)__cvta_generic_to_shared(&sAsg[buf][0]);
        unsigned bBB  = (unsigned)__cvta_generic_to_shared(&sB[buf][0]);
        #pragma unroll
        for (int k16 = 0; k16 < 4; k16++) {
            int ag = (k16 * 2 + agadd) ^ l7;
            int bg = (k16 * 2 + bgadd) ^ l7;
            unsigned aaddr = bApm + ((arow * 8 + ag) << 4);
            unsigned saddr = bAsg + ((arow * 8 + ag) << 4);
            unsigned baddr = bBB  + ((brow * 8 + bg) << 4);
            unsigned a0, a1, a2, a3, d0, d1, d2, d3, e0, e1, e2, e3;
            asm volatile("ldmatrix.sync.aligned.m8n8.x4.shared.b16 {%0,%1,%2,%3},[%4];\n"
                         : "=r"(a0), "=r"(a1), "=r"(a2), "=r"(a3) : "r"(aaddr));
            asm volatile("ldmatrix.sync.aligned.m8n8.x4.shared.b16 {%0,%1,%2,%3},[%4];\n"
                         : "=r"(d0), "=r"(d1), "=r"(d2), "=r"(d3) : "r"(saddr));
            asm volatile("ldmatrix.sync.aligned.m8n8.x4.shared.b16 {%0,%1,%2,%3},[%4];\n"
                         : "=r"(e0), "=r"(e1), "=r"(e2), "=r"(e3) : "r"(baddr));
            mma16816(cA[0], a0, a1, a2, a3, e0, e1);
            mma16816(cA[1], a0, a1, a2, a3, e2, e3);
            mma16816(cD[0], d0, d1, d2, d3, e0, e1);
            mma16816(cD[1], d0, d1, d2, d3, e2, e3);
        }
        __syncthreads();
    }

    // Epilogue: write fp32 partials. g_part[b][ks][g][row][t]
    int r0 = q0 + mw * 16 + (lane >> 2);
    int c0 = 2 * (lane & 3);
    #pragma unroll
    for (int g = 0; g < 2; g++) {
        float (*cc)[4] = g ? cD : cA;
        size_t pb = (((size_t)(b * KSLAB + ks) * 2 + g) * MPAD) * T_;
        #pragma unroll
        for (int nt = 0; nt < 2; nt++) {
            int col = nw * 16 + nt * 8 + c0;
            float2 v0 = make_float2(cc[nt][0], cc[nt][1]);
            float2 v1 = make_float2(cc[nt][2], cc[nt][3]);
            *(float2*)&g_part[pb + (size_t)r0 * T_ + col]       = v0;
            *(float2*)&g_part[pb + (size_t)(r0 + 8) * T_ + col] = v1;
        }
    }
}

// Final: reduce partials + class cost + combine. Grid (Q_, B_), 32 threads.
__global__ __launch_bounds__(32) void k_final(
    const float* __restrict__ clslog, const int* __restrict__ labels,
    float* __restrict__ out) {
    int q = blockIdx.x, b = blockIdx.y;
    int t = threadIdx.x;

    float A = 0.f, D = 0.f;
    #pragma unroll
    for (int ks = 0; ks < KSLAB; ks++) {
        size_t pb = ((size_t)(b * KSLAB + ks) * 2) * MPAD * T_;
        A += g_part[pb + (size_t)q * T_ + t];
        D += g_part[pb + (size_t)(MPAD * T_) + (size_t)q * T_ + t];
    }
    float Sneg = g_S[(b * Q_ + q) * 2 + 0];
    float Ssig = g_S[(b * Q_ + q) * 2 + 1];

    const float* cl = clslog + (size_t)(b * Q_ + q) * C_;
    float lmax = -1e30f;
    for (int c = t; c < C_; c += 32) lmax = fmaxf(lmax, cl[c]);
    #pragma unroll
    for (int off = 16; off; off >>= 1)
        lmax = fmaxf(lmax, __shfl_xor_sync(~0u, lmax, off));
    float lsum = 0.f;
    for (int c = t; c < C_; c += 32) lsum += __expf(cl[c] - lmax);
    #pragma unroll
    for (int off = 16; off; off >>= 1)
        lsum += __shfl_xor_sync(~0u, lsum, off);

    int lbl = labels[b * T_ + t];
    lbl = min(max(lbl, 0), C_ - 1);
    float cost_class = -__expf(cl[lbl] - lmax) / lsum;
    float Stm = g_Stm[b * T_ + t];
    float cost_mask = 5.f * (Sneg - A) * (1.f / (float)P_);
    float cost_dice = 5.f * (1.f - (2.f * D + 1.f) / (Ssig + Stm + 1.f));
    out[((size_t)(b * Q_ + q)) * T_ + t] = cost_mask + cost_class + cost_dice;
}

extern "C" void kernel_launch(void* const* d_in, const int* in_sizes, int n_in,
                              void* d_out, int out_size) {
    const float* pmask  = (const float*)d_in[0];  // [8,150,160,160]
    const float* clslog = (const float*)d_in[1];  // [8,150,134]
    const float* tmask  = (const float*)d_in[2];  // [8,32,160,160]
    const int*   labels = (const int*)d_in[3];    // [8,32] int32
    const float* coords = (const float*)d_in[4];  // [8,12544,2]
    float* out = (float*)d_out;                   // [8,150,32]

    const int smem1 = (HW_ + 16) * 4;
    cudaFuncSetAttribute(k_sample, cudaFuncAttributeMaxDynamicSharedMemorySize, smem1);

    k_sample<<<dim3(T_ + Q_, B_), 256, smem1>>>(pmask, tmask, coords);
    k_gemm  <<<dim3(3, KSLAB, B_), 256>>>();
    k_final <<<dim3(Q_, B_), 32>>>(clslog, labels, out);
}

// round 6
// speedup vs baseline: 3.2130x; 1.2067x over previous
#include <cuda_runtime.h>
#include <cuda_fp16.h>
#include <math.h>

#define B_ 8
#define Q_ 150
#define C_ 134
#define T_ 32
#define H_ 160
#define W_ 160
#define P_ 12544
#define HW_ (H_ * W_)
#define MPAD 192           // Q padded to 3 x 64
#define KSLAB 14
#define KCH 896            // P_/KSLAB
#define NSTAGE 14          // KCH/64

// Static scratch (zero-initialized at module load; rows q>=150 of g_pm/g_sig
// are never written and stay 0 -> padded GEMM rows contribute nothing).
__device__ __align__(128) __half g_tmT[(size_t)B_ * T_ * P_];      // [b][t][p]
__device__ __align__(128) __half g_pm [(size_t)B_ * MPAD * P_];    // [b][q][p]
__device__ __align__(128) __half g_sig[(size_t)B_ * MPAD * P_];    // [b][q][p]
__device__ float g_S[B_ * Q_ * 2];                                 // Sneg, Ssig
__device__ float g_Stm[B_ * T_];
__device__ __align__(128) float g_part[(size_t)B_ * KSLAB * 2 * MPAD * T_];
// Precomputed bilinear taps: packed base|dx|dy and 4 fp16 weights per (b,p).
__device__ __align__(128) int   g_off[(size_t)B_ * P_];
__device__ __align__(128) uint2 g_wts[(size_t)B_ * P_];

// Precompute bilinear gather offsets + weights (align_corners=False, zero pad).
// Grid (P_/256, B_), 256 threads.
__global__ __launch_bounds__(256) void k_prep(const float* __restrict__ coords) {
    int p = blockIdx.x * 256 + threadIdx.x;
    int b = blockIdx.y;
    float2 c = ((const float2*)coords)[(size_t)b * P_ + p];
    float x = c.x * (float)W_ - 0.5f;
    float y = c.y * (float)H_ - 0.5f;
    float fx = floorf(x), fy = floorf(y);
    float tx = x - fx, ty = y - fy;
    int x0 = (int)fx, y0 = (int)fy;  // in [-1, 159]
    float wx0 = (1.f - tx) * (x0 >= 0 ? 1.f : 0.f);
    float wx1 = tx         * (x0 < W_ - 1 ? 1.f : 0.f);
    float wy0 = (1.f - ty) * (y0 >= 0 ? 1.f : 0.f);
    float wy1 = ty         * (y0 < H_ - 1 ? 1.f : 0.f);
    int xc0 = max(x0, 0), yc0 = max(y0, 0);
    int dx = (x0 >= 0 && x0 < W_ - 1) ? 1 : 0;  // xc1 - xc0
    int dy = (y0 >= 0 && y0 < H_ - 1) ? 1 : 0;  // yc1 - yc0
    int base = yc0 * W_ + xc0;                  // < 25600 (15 bits)
    g_off[(size_t)b * P_ + p] = base | (dx << 15) | (dy << 16);
    uint2 w;
    __half2 wlo = __floats2half2_rn(wx0 * wy0, wx1 * wy0);  // w00, w01
    __half2 whi = __floats2half2_rn(wx0 * wy1, wx1 * wy1);  // w10, w11
    w.x = *(unsigned*)&wlo;
    w.y = *(unsigned*)&whi;
    g_wts[(size_t)b * P_ + p] = w;
}

// Unified sampler. Grid (T_ + Q_, B_), 256 threads. Mask held as fp16 in smem
// (51.2 KB -> 4 CTAs/SM). Per point: 2 LDG (taps) + 4 LDS.U16 + dot.
// blockIdx.x < T_  : target mask t -> g_tmT[b][t][p] + g_Stm
// blockIdx.x >= T_ : pred mask  q -> g_pm/g_sig[b][q][p] + g_S
__global__ __launch_bounds__(256) void k_sample(
    const float* __restrict__ pmask, const float* __restrict__ tgt) {
    extern __shared__ __half sh[];           // HW_ halves (fp16 mask)
    float* swr = (float*)(sh + HW_);         // 16 floats reduction scratch
    int bx = blockIdx.x, b = blockIdx.y;
    int tid = threadIdx.x;
    bool is_tgt = bx < T_;

    const float* src = is_tgt ? tgt + ((size_t)(b * T_ + bx)) * HW_
                              : pmask + ((size_t)(b * Q_ + (bx - T_))) * HW_;
    const float4* m4 = (const float4*)src;
    __half2* dst = (__half2*)sh;
    for (int i = tid; i < HW_ / 4; i += 256) {
        float4 v = m4[i];
        dst[2 * i]     = __floats2half2_rn(v.x, v.y);
        dst[2 * i + 1] = __floats2half2_rn(v.z, v.w);
    }
    __syncthreads();

    const int*   offs = g_off + (size_t)b * P_;
    const uint2* wts  = g_wts + (size_t)b * P_;

    if (is_tgt) {
        int t = bx;
        __half* out = g_tmT + ((size_t)(b * T_ + t)) * P_;
        float sum = 0.f;
        #pragma unroll 7
        for (int it = 0; it < 49; it++) {
            int p = tid + it * 256;
            int pk = offs[p];
            uint2 wr = wts[p];
            int base = pk & 0x7FFF;
            int dx = (pk >> 15) & 1;
            int dW = ((pk >> 16) & 1) * W_;
            float2 wlo = __half22float2(*(__half2*)&wr.x);
            float2 whi = __half22float2(*(__half2*)&wr.y);
            float v = __half2float(sh[base]) * wlo.x
                    + __half2float(sh[base + dx]) * wlo.y
                    + __half2float(sh[base + dW]) * whi.x
                    + __half2float(sh[base + dW + dx]) * whi.y;
            out[p] = __float2half_rn(v);
            sum += v;
        }
        #pragma unroll
        for (int off = 16; off; off >>= 1) sum += __shfl_xor_sync(~0u, sum, off);
        if ((tid & 31) == 0) swr[tid >> 5] = sum;
        __syncthreads();
        if (tid == 0) {
            float s = 0.f;
            #pragma unroll
            for (int w = 0; w < 8; w++) s += swr[w];
            g_Stm[b * T_ + t] = s;
        }
    } else {
        int q = bx - T_;
        __half* opm = g_pm  + ((size_t)(b * MPAD + q)) * P_;
        __half* osg = g_sig + ((size_t)(b * MPAD + q)) * P_;
        float sNeg = 0.f, sSig = 0.f;
        #pragma unroll 7
        for (int it = 0; it < 49; it++) {
            int p = tid + it * 256;
            int pk = offs[p];
            uint2 wr = wts[p];
            int base = pk & 0x7FFF;
            int dx = (pk >> 15) & 1;
            int dW = ((pk >> 16) & 1) * W_;
            float2 wlo = __half22float2(*(__half2*)&wr.x);
            float2 whi = __half22float2(*(__half2*)&wr.y);
            float pm = __half2float(sh[base]) * wlo.x
                     + __half2float(sh[base + dx]) * wlo.y
                     + __half2float(sh[base + dW]) * whi.x
                     + __half2float(sh[base + dW + dx]) * whi.y;
            float ea  = __expf(-fabsf(pm));
            float r   = __frcp_rn(1.f + ea);
            float sig = (pm >= 0.f) ? r : ea * r;
            float sp  = fmaxf(pm, 0.f) + __logf(1.f + ea);  // softplus(pm)
            sSig += sig;
            sNeg += sp;
            opm[p] = __float2half_rn(pm);
            osg[p] = __float2half_rn(sig);
        }
        #pragma unroll
        for (int off = 16; off; off >>= 1) {
            sNeg += __shfl_xor_sync(~0u, sNeg, off);
            sSig += __shfl_xor_sync(~0u, sSig, off);
        }
        if ((tid & 31) == 0) { swr[tid >> 5] = sNeg; swr[8 + (tid >> 5)] = sSig; }
        __syncthreads();
        if (tid == 0) {
            float a = 0.f, d = 0.f;
            #pragma unroll
            for (int w = 0; w < 8; w++) { a += swr[w]; d += swr[8 + w]; }
            g_S[(b * Q_ + q) * 2 + 0] = a;
            g_S[(b * Q_ + q) * 2 + 1] = d;
        }
    }
}

__device__ __forceinline__ void mma16816(float* c, unsigned a0, unsigned a1,
                                         unsigned a2, unsigned a3,
                                         unsigned b0, unsigned b1) {
    asm volatile(
        "mma.sync.aligned.m16n8k16.row.col.f32.f16.f16.f32 "
        "{%0,%1,%2,%3},{%4,%5,%6,%7},{%8,%9},{%0,%1,%2,%3};\n"
        : "+f"(c[0]), "+f"(c[1]), "+f"(c[2]), "+f"(c[3])
        : "r"(a0), "r"(a1), "r"(a2), "r"(a3), "r"(b0), "r"(b1));
}

// Batched split-K GEMM on tensor cores.
// C_A[q,t] = sum_p pm[q,p]*tmT[t,p]; C_D likewise with sig.
// Grid (3 mblk, KSLAB, B_), 256 threads = 8 warps (4 m-warps x 2 n-warps).
__global__ __launch_bounds__(256) void k_gemm() {
    __shared__ uint4 sApm[2][512];   // 64 rows x 8 granules(16B), XOR-swizzled
    __shared__ uint4 sAsg[2][512];
    __shared__ uint4 sB[2][256];     // 32 rows x 8 granules
    int mblk = blockIdx.x, ks = blockIdx.y, b = blockIdx.z;
    int tid = threadIdx.x;
    int q0 = mblk * 64;
    size_t baseA = ((size_t)b * MPAD + q0) * P_ + (size_t)ks * KCH;
    size_t baseB = ((size_t)b * T_) * P_ + (size_t)ks * KCH;

    auto stage = [&](int s, int buf) {
        int kg = s * 64;
        #pragma unroll
        for (int i = 0; i < 5; i++) {
            int gid = tid + i * 256;
            const __half* src;
            uint4* dst;
            int r, c;
            if (gid < 512) {
                r = gid >> 3; c = gid & 7;
                src = g_pm + baseA + (size_t)r * P_ + kg + c * 8;
                dst = &sApm[buf][0];
            } else if (gid < 1024) {
                int g2 = gid - 512; r = g2 >> 3; c = g2 & 7;
                src = g_sig + baseA + (size_t)r * P_ + kg + c * 8;
                dst = &sAsg[buf][0];
            } else {
                int g2 = gid - 1024; r = g2 >> 3; c = g2 & 7;
                src = g_tmT + baseB + (size_t)r * P_ + kg + c * 8;
                dst = &sB[buf][0];
            }
            unsigned d32 = (unsigned)__cvta_generic_to_shared(dst + r * 8 + (c ^ (r & 7)));
            asm volatile("cp.async.cg.shared.global [%0], [%1], 16;\n"
                         :: "r"(d32), "l"(src));
        }
        asm volatile("cp.async.commit_group;\n");
    };

    int warp = tid >> 5, lane = tid & 31;
    int mw = warp >> 1, nw = warp & 1;
    int lm = lane >> 3, l7 = lane & 7;
    int arow = mw * 16 + ((lm & 1) << 3) + l7;   // A ldmatrix row per lane
    int agadd = lm >> 1;                          // k8-half select
    int brow = nw * 16 + ((lm >> 1) << 3) + l7;  // B ldmatrix row per lane
    int bgadd = lm & 1;

    float cA[2][4] = {}, cD[2][4] = {};

    stage(0, 0);
    for (int s = 0; s < NSTAGE; s++) {
        int buf = s & 1;
        if (s + 1 < NSTAGE) {
            stage(s + 1, buf ^ 1);
            asm volatile("cp.async.wait_group 1;\n");
        } else {
            asm volatile("cp.async.wait_group 0;\n");
        }
        __syncthreads();
        unsigned bApm = (unsigned)__cvta_generic_to_shared(&sApm[buf][0]);
        unsigned bAsg = (unsigned)__cvta_generic_to_shared(&sAsg[buf][0]);
        unsigned bBB  = (unsigned)__cvta_generic_to_shared(&sB[buf][0]);
        #pragma unroll
        for (int k16 = 0; k16 < 4; k16++) {
            int ag = (k16 * 2 + agadd) ^ l7;
            int bg = (k16 * 2 + bgadd) ^ l7;
            unsigned aaddr = bApm + ((arow * 8 + ag) << 4);
            unsigned saddr = bAsg + ((arow * 8 + ag) << 4);
            unsigned baddr = bBB  + ((brow * 8 + bg) << 4);
            unsigned a0, a1, a2, a3, d0, d1, d2, d3, e0, e1, e2, e3;
            asm volatile("ldmatrix.sync.aligned.m8n8.x4.shared.b16 {%0,%1,%2,%3},[%4];\n"
                         : "=r"(a0), "=r"(a1), "=r"(a2), "=r"(a3) : "r"(aaddr));
            asm volatile("ldmatrix.sync.aligned.m8n8.x4.shared.b16 {%0,%1,%2,%3},[%4];\n"
                         : "=r"(d0), "=r"(d1), "=r"(d2), "=r"(d3) : "r"(saddr));
            asm volatile("ldmatrix.sync.aligned.m8n8.x4.shared.b16 {%0,%1,%2,%3},[%4];\n"
                         : "=r"(e0), "=r"(e1), "=r"(e2), "=r"(e3) : "r"(baddr));
            mma16816(cA[0], a0, a1, a2, a3, e0, e1);
            mma16816(cA[1], a0, a1, a2, a3, e2, e3);
            mma16816(cD[0], d0, d1, d2, d3, e0, e1);
            mma16816(cD[1], d0, d1, d2, d3, e2, e3);
        }
        __syncthreads();
    }

    // Epilogue: write fp32 partials. g_part[b][ks][g][row][t]
    int r0 = q0 + mw * 16 + (lane >> 2);
    int c0 = 2 * (lane & 3);
    #pragma unroll
    for (int g = 0; g < 2; g++) {
        float (*cc)[4] = g ? cD : cA;
        size_t pb = (((size_t)(b * KSLAB + ks) * 2 + g) * MPAD) * T_;
        #pragma unroll
        for (int nt = 0; nt < 2; nt++) {
            int col = nw * 16 + nt * 8 + c0;
            float2 v0 = make_float2(cc[nt][0], cc[nt][1]);
            float2 v1 = make_float2(cc[nt][2], cc[nt][3]);
            *(float2*)&g_part[pb + (size_t)r0 * T_ + col]       = v0;
            *(float2*)&g_part[pb + (size_t)(r0 + 8) * T_ + col] = v1;
        }
    }
}

// Final: reduce partials + class cost + combine. Grid (Q_, B_), 32 threads.
__global__ __launch_bounds__(32) void k_final(
    const float* __restrict__ clslog, const int* __restrict__ labels,
    float* __restrict__ out) {
    int q = blockIdx.x, b = blockIdx.y;
    int t = threadIdx.x;

    float A = 0.f, D = 0.f;
    #pragma unroll
    for (int ks = 0; ks < KSLAB; ks++) {
        size_t pb = ((size_t)(b * KSLAB + ks) * 2) * MPAD * T_;
        A += g_part[pb + (size_t)q * T_ + t];
        D += g_part[pb + (size_t)(MPAD * T_) + (size_t)q * T_ + t];
    }
    float Sneg = g_S[(b * Q_ + q) * 2 + 0];
    float Ssig = g_S[(b * Q_ + q) * 2 + 1];

    const float* cl = clslog + (size_t)(b * Q_ + q) * C_;
    float lmax = -1e30f;
    for (int c = t; c < C_; c += 32) lmax = fmaxf(lmax, cl[c]);
    #pragma unroll
    for (int off = 16; off; off >>= 1)
        lmax = fmaxf(lmax, __shfl_xor_sync(~0u, lmax, off));
    float lsum = 0.f;
    for (int c = t; c < C_; c += 32) lsum += __expf(cl[c] - lmax);
    #pragma unroll
    for (int off = 16; off; off >>= 1)
        lsum += __shfl_xor_sync(~0u, lsum, off);

    int lbl = labels[b * T_ + t];
    lbl = min(max(lbl, 0), C_ - 1);
    float cost_class = -__expf(cl[lbl] - lmax) / lsum;
    float Stm = g_Stm[b * T_ + t];
    float cost_mask = 5.f * (Sneg - A) * (1.f / (float)P_);
    float cost_dice = 5.f * (1.f - (2.f * D + 1.f) / (Ssig + Stm + 1.f));
    out[((size_t)(b * Q_ + q)) * T_ + t] = cost_mask + cost_class + cost_dice;
}

extern "C" void kernel_launch(void* const* d_in, const int* in_sizes, int n_in,
                              void* d_out, int out_size) {
    const float* pmask  = (const float*)d_in[0];  // [8,150,160,160]
    const float* clslog = (const float*)d_in[1];  // [8,150,134]
    const float* tmask  = (const float*)d_in[2];  // [8,32,160,160]
    const int*   labels = (const int*)d_in[3];    // [8,32] int32
    const float* coords = (const float*)d_in[4];  // [8,12544,2]
    float* out = (float*)d_out;                   // [8,150,32]

    const int smem1 = HW_ * 2 + 64;               // fp16 mask + reduction scratch
    cudaFuncSetAttribute(k_sample, cudaFuncAttributeMaxDynamicSharedMemorySize, smem1);

    k_prep  <<<dim3(P_ / 256, B_), 256>>>(coords);
    k_sample<<<dim3(T_ + Q_, B_), 256, smem1>>>(pmask, tmask);
    k_gemm  <<<dim3(3, KSLAB, B_), 256>>>();
    k_final <<<dim3(Q_, B_), 32>>>(clslog, labels, out);
}